// round 6
// baseline (speedup 1.0000x reference)
#include <cuda_runtime.h>
#include <cuda_bf16.h>
#include <math.h>
#include <stdint.h>

// Problem constants (fixed by the reference)
#define BB 2
#define SS 2048
#define DD 512
#define VV 32000
#define HH 4
#define DH 128
#define WW 3
#define NN (BB*SS)   // 4096
#define KP 1536      // GAT split-bf16 K' = 3*512
#define NCH_GAT 24   // KP / 64
#define NCH_LM  24   // 3 * 512 / 64  (three products, BK=64)

// Scratch (device globals; no allocation allowed)
__device__ float g_x   [NN*DD];
__device__ float g_x2  [NN*DD];
__device__ float g_wx  [NN*DD];
__device__ float g_agg [NN*DD];
__device__ float g_ssrc[NN*HH];
__device__ float g_sdst[NN*HH];
__device__ __nv_bfloat16 g_Ap[(size_t)NN*KP];   // GAT A split [Ah|Ah|Al]
__device__ __nv_bfloat16 g_Wp[(size_t)DD*KP];   // GAT W split [Bh|Bl|Bh]
__device__ __nv_bfloat16 g_Ah[(size_t)NN*DD];   // LM head A hi
__device__ __nv_bfloat16 g_Al[(size_t)NN*DD];   // LM head A lo
__device__ __nv_bfloat16 g_Bh[(size_t)VV*DD];   // LM head B hi
__device__ __nv_bfloat16 g_Bl[(size_t)VV*DD];   // LM head B lo

// ---------------------------------------------------------------------------
// PTX helpers (sm_80-era: cp.async, ldmatrix, mma.sync — valid at compute_103.
// tcgen05 is NOT available at the harness's virtual PTX target.)
// ---------------------------------------------------------------------------
__device__ __forceinline__ uint32_t smem_u32(const void* p) {
    uint32_t a;
    asm("{ .reg .u64 t; cvta.to.shared.u64 t, %1; cvt.u32.u64 %0, t; }"
        : "=r"(a) : "l"(p));
    return a;
}
__device__ __forceinline__ void cp_async16(uint32_t dst, const void* src) {
    asm volatile("cp.async.cg.shared.global [%0], [%1], 16;\n" :: "r"(dst), "l"(src));
}
#define CP_COMMIT() asm volatile("cp.async.commit_group;\n" ::: "memory")
template<int Nw> __device__ __forceinline__ void cp_wait() {
    asm volatile("cp.async.wait_group %0;\n" :: "n"(Nw) : "memory");
}
__device__ __forceinline__ void ldmatrix_x4(uint32_t& r0, uint32_t& r1,
                                            uint32_t& r2, uint32_t& r3, uint32_t addr) {
    asm volatile("ldmatrix.sync.aligned.m8n8.x4.shared.b16 {%0,%1,%2,%3}, [%4];\n"
                 : "=r"(r0), "=r"(r1), "=r"(r2), "=r"(r3) : "r"(addr));
}
__device__ __forceinline__ void mma_bf16(float* c,
                                         uint32_t a0, uint32_t a1, uint32_t a2, uint32_t a3,
                                         uint32_t b0, uint32_t b1) {
    asm volatile(
        "mma.sync.aligned.m16n8k16.row.col.f32.bf16.bf16.f32 "
        "{%0,%1,%2,%3}, {%4,%5,%6,%7}, {%8,%9}, {%0,%1,%2,%3};\n"
        : "+f"(c[0]), "+f"(c[1]), "+f"(c[2]), "+f"(c[3])
        : "r"(a0), "r"(a1), "r"(a2), "r"(a3), "r"(b0), "r"(b1));
}

// ---------------------------------------------------------------------------
// Embedding gather
// ---------------------------------------------------------------------------
__global__ void gather_k(const int* __restrict__ ids,
                         const float* __restrict__ emb,
                         float* __restrict__ x)
{
    int idx = blockIdx.x * blockDim.x + threadIdx.x;
    int n  = idx / (DD/4);
    int d4 = idx % (DD/4);
    const float4* srcp = (const float4*)(emb + (size_t)ids[n]*DD) + d4;
    float4* dstp = (float4*)(x + (size_t)n*DD) + d4;
    *dstp = *srcp;
}

// ---------------------------------------------------------------------------
// GAT conversions: fp32 -> K-concatenated bf16 splits
// ---------------------------------------------------------------------------
__global__ void conv_A_k(const float* __restrict__ src, __nv_bfloat16* __restrict__ dst)
{
    size_t i = (size_t)blockIdx.x * blockDim.x + threadIdx.x;
    size_t r = i / (DD/4);
    int c = (int)(i % (DD/4)) * 4;
    float4 v = *(const float4*)(src + r*DD + c);
    float f[4] = {v.x, v.y, v.z, v.w};
    __nv_bfloat16* base = dst + r*KP + c;
    #pragma unroll
    for (int j = 0; j < 4; j++) {
        __nv_bfloat16 h = __float2bfloat16(f[j]);
        __nv_bfloat16 l = __float2bfloat16(f[j] - __bfloat162float(h));
        base[j]        = h;
        base[512 + j]  = h;
        base[1024 + j] = l;
    }
}
__global__ void conv_B_k(const float* __restrict__ src, __nv_bfloat16* __restrict__ dst)
{
    size_t i = (size_t)blockIdx.x * blockDim.x + threadIdx.x;
    size_t r = i / (DD/4);
    int c = (int)(i % (DD/4)) * 4;
    float4 v = *(const float4*)(src + r*DD + c);
    float f[4] = {v.x, v.y, v.z, v.w};
    __nv_bfloat16* base = dst + r*KP + c;
    #pragma unroll
    for (int j = 0; j < 4; j++) {
        __nv_bfloat16 h = __float2bfloat16(f[j]);
        __nv_bfloat16 l = __float2bfloat16(f[j] - __bfloat162float(h));
        base[j]        = h;
        base[512 + j]  = l;
        base[1024 + j] = h;
    }
}

// ---------------------------------------------------------------------------
// LM-head conversions: fp32 -> (hi, lo) bf16 pair arrays
// ---------------------------------------------------------------------------
__global__ void conv_hl_k(const float* __restrict__ src,
                          __nv_bfloat16* __restrict__ dh, __nv_bfloat16* __restrict__ dl)
{
    size_t i = (size_t)blockIdx.x * blockDim.x + threadIdx.x;
    size_t r = i / (DD/4);
    int c = (int)(i % (DD/4)) * 4;
    float4 v = *(const float4*)(src + r*DD + c);
    float f[4] = {v.x, v.y, v.z, v.w};
    #pragma unroll
    for (int j = 0; j < 4; j++) {
        __nv_bfloat16 h = __float2bfloat16(f[j]);
        __nv_bfloat16 l = __float2bfloat16(f[j] - __bfloat162float(h));
        dh[r*DD + c + j] = h;
        dl[r*DD + c + j] = l;
    }
}

// ---------------------------------------------------------------------------
// Per-node attention scores
// ---------------------------------------------------------------------------
__global__ void scores_k(const float* __restrict__ wx,
                         const float* __restrict__ a,
                         float* __restrict__ ssrc,
                         float* __restrict__ sdst)
{
    int w    = (blockIdx.x * blockDim.x + threadIdx.x) >> 5;
    int lane = threadIdx.x & 31;
    if (w >= NN*HH) return;
    int n = w / HH, h = w % HH;
    const float* row = wx + (size_t)n*DD + h*DH;
    const float* au  = a + (size_t)h*2*DH;
    const float* av  = au + DH;

    int d = lane * 4;
    float4 x = *(const float4*)(row + d);
    float4 u = *(const float4*)(au  + d);
    float4 v = *(const float4*)(av  + d);
    float s1 = x.x*u.x + x.y*u.y + x.z*u.z + x.w*u.w;
    float s2 = x.x*v.x + x.y*v.y + x.z*v.z + x.w*v.w;
    #pragma unroll
    for (int o = 16; o; o >>= 1) {
        s1 += __shfl_xor_sync(0xffffffffu, s1, o);
        s2 += __shfl_xor_sync(0xffffffffu, s2, o);
    }
    if (lane == 0) { ssrc[w] = s1; sdst[w] = s2; }
}

// ---------------------------------------------------------------------------
// Windowed GAT aggregation
// ---------------------------------------------------------------------------
__global__ void attn_k(const float* __restrict__ wx,
                       const float* __restrict__ ssrc,
                       const float* __restrict__ sdst,
                       float* __restrict__ agg)
{
    int n    = blockIdx.x;
    int h    = threadIdx.x >> 5;
    int lane = threadIdx.x & 31;
    int i    = n % SS;

    float sd = sdst[(size_t)n*HH + h];

    float e[2*WW];
    int   jn[2*WW];
    int cnt = 0;
    #pragma unroll
    for (int off = -WW; off <= WW; off++) {
        if (off == 0) continue;
        int ji = i + off;
        if (ji < 0 || ji >= SS) continue;
        int j = n + off;
        float v = ssrc[(size_t)j*HH + h] + sd;
        v = v >= 0.f ? v : 0.2f * v;
        e[cnt] = v; jn[cnt] = j; cnt++;
    }
    float m = -1e30f;
    for (int c = 0; c < cnt; c++) m = fmaxf(m, e[c]);
    float den = 0.f;
    for (int c = 0; c < cnt; c++) { e[c] = expf(e[c] - m); den += e[c]; }
    float inv = 1.f / (den + 1e-16f);

    int d = lane * 4;
    float4 accv = make_float4(0.f, 0.f, 0.f, 0.f);
    for (int c = 0; c < cnt; c++) {
        const float4 xv = *(const float4*)(wx + (size_t)jn[c]*DD + h*DH + d);
        float al = e[c] * inv;
        accv.x = fmaf(al, xv.x, accv.x);
        accv.y = fmaf(al, xv.y, accv.y);
        accv.z = fmaf(al, xv.z, accv.z);
        accv.w = fmaf(al, xv.w, accv.w);
    }
    *(float4*)(agg + (size_t)n*DD + h*DH + d) = accv;
}

// ---------------------------------------------------------------------------
// GAT mma GEMM (split-bf16 K'=1536): unchanged (passing, small share of time)
// ---------------------------------------------------------------------------
#define G_STAGES 3
#define G_STAGE_BYTES 32768
#define G_SMEM (G_STAGES*G_STAGE_BYTES)

__device__ __forceinline__ void load_stage_gat(
    const __nv_bfloat16* __restrict__ Ap, const __nv_bfloat16* __restrict__ Bp,
    int row0, int col0, int k0, uint32_t stage_base, int tid)
{
    #pragma unroll
    for (int it = 0; it < 8; it++) {
        int g = tid + it*256;
        bool isA = (g < 1024);
        int gg  = isA ? g : (g - 1024);
        int row = gg >> 3;
        int gran = gg & 7;
        const __nv_bfloat16* src = isA
            ? (Ap + (size_t)(row0 + row)*KP + k0 + gran*8)
            : (Bp + (size_t)(col0 + row)*KP + k0 + gran*8);
        uint32_t dst = stage_base + (isA ? 0u : 16384u)
                     + (uint32_t)row*128u + (uint32_t)((gran ^ (row & 7)) << 4);
        cp_async16(dst, src);
    }
}

template<int EPI>
__global__ void __launch_bounds__(256, 2)
gat_mma_k(const __nv_bfloat16* __restrict__ Ap,
          const __nv_bfloat16* __restrict__ Bp,
          const float* __restrict__ bias,
          float* __restrict__ C)
{
    extern __shared__ char smem[];
    const uint32_t sb = smem_u32(smem);
    const int tid  = threadIdx.x;
    const int wid  = tid >> 5;
    const int lane = tid & 31;
    const int row0 = blockIdx.x * 128;
    const int col0 = blockIdx.y * 128;

    const int warp_m = wid & 3;
    const int warp_n = wid >> 2;

    float acc[2][8][4];
    #pragma unroll
    for (int i = 0; i < 2; i++)
        #pragma unroll
        for (int j = 0; j < 8; j++)
            #pragma unroll
            for (int q = 0; q < 4; q++) acc[i][j][q] = 0.f;

    load_stage_gat(Ap, Bp, row0, col0, 0,  sb,                 tid); CP_COMMIT();
    load_stage_gat(Ap, Bp, row0, col0, 64, sb + G_STAGE_BYTES, tid); CP_COMMIT();

    const int a_row  = warp_m*32 + (lane & 15);
    const int a_gsel = lane >> 4;
    const int b_row  = warp_n*64 + ((lane >> 4) << 3) + (lane & 7);
    const int b_gsel = (lane >> 3) & 1;

    for (int c = 0; c < NCH_GAT; c++) {
        cp_wait<G_STAGES-2>();
        __syncthreads();

        if (c + 2 < NCH_GAT)
            load_stage_gat(Ap, Bp, row0, col0, (c+2)*64,
                           sb + ((c+2)%G_STAGES)*G_STAGE_BYTES, tid);
        CP_COMMIT();

        const uint32_t sA = sb + (c%G_STAGES)*G_STAGE_BYTES;
        const uint32_t sB = sA + 16384u;

        #pragma unroll
        for (int s = 0; s < 4; s++) {
            uint32_t a[2][4];
            #pragma unroll
            for (int mi = 0; mi < 2; mi++) {
                int r = a_row + mi*16;
                int gran = 2*s + a_gsel;
                uint32_t addr = sA + (uint32_t)r*128u + (uint32_t)((gran ^ (r & 7)) << 4);
                ldmatrix_x4(a[mi][0], a[mi][1], a[mi][2], a[mi][3], addr);
            }
            uint32_t b[8][2];
            #pragma unroll
            for (int ng = 0; ng < 4; ng++) {
                int r = b_row + ng*16;
                int gran = 2*s + b_gsel;
                uint32_t addr = sB + (uint32_t)r*128u + (uint32_t)((gran ^ (r & 7)) << 4);
                uint32_t r0, r1, r2, r3;
                ldmatrix_x4(r0, r1, r2, r3, addr);
                b[ng*2+0][0] = r0; b[ng*2+0][1] = r1;
                b[ng*2+1][0] = r2; b[ng*2+1][1] = r3;
            }
            #pragma unroll
            for (int mi = 0; mi < 2; mi++)
                #pragma unroll
                for (int nj = 0; nj < 8; nj++)
                    mma_bf16(acc[mi][nj], a[mi][0], a[mi][1], a[mi][2], a[mi][3],
                             b[nj][0], b[nj][1]);
        }
    }

    const int trow = lane >> 2;
    const int tcol = (lane & 3) * 2;
    #pragma unroll
    for (int mi = 0; mi < 2; mi++) {
        const int mbase = row0 + warp_m*32 + mi*16 + trow;
        #pragma unroll
        for (int nj = 0; nj < 8; nj++) {
            const int col = col0 + warp_n*64 + nj*8 + tcol;
            float vv[4] = {acc[mi][nj][0], acc[mi][nj][1], acc[mi][nj][2], acc[mi][nj][3]};
            if (EPI == 1) {
                const float b0 = __ldg(bias + col);
                const float b1 = __ldg(bias + col + 1);
                vv[0] += b0; vv[1] += b1; vv[2] += b0; vv[3] += b1;
                #pragma unroll
                for (int q = 0; q < 4; q++)
                    vv[q] = vv[q] > 0.f ? vv[q] : (expf(vv[q]) - 1.f);
            }
            *(float2*)(C + (size_t)mbase*DD + col)     = make_float2(vv[0], vv[1]);
            *(float2*)(C + (size_t)(mbase+8)*DD + col) = make_float2(vv[2], vv[3]);
        }
    }
}

// ---------------------------------------------------------------------------
// LM head v4: C = Ah@Bh^T + Ah@Bl^T + Al@Bh^T + bias  (exact split-3, bf16)
// CTA 128x128; 8 warps (2m x 4n), warp tile 64x32 -> 4 warps/SMSP at occ 2.
// BK=64, 3-stage cp.async, 96KB smem, ~120 regs.
// K-loop: 24 chunks: c<8 Ah*Bh, 8<=c<16 Ah*Bl, c>=16 Al*Bh.
// ---------------------------------------------------------------------------
#define L_STAGES 3
#define L_STAGE_BYTES 32768   // A 16KB + B 16KB
#define L_SMEM (L_STAGES*L_STAGE_BYTES)

__device__ __forceinline__ void load_stage_lm(
    const __nv_bfloat16* __restrict__ A, const __nv_bfloat16* __restrict__ B,
    int row0, int col0, int kk, uint32_t stage_base, int tid)
{
    #pragma unroll
    for (int it = 0; it < 8; it++) {
        int g = tid + it*256;          // 0..2047
        bool isA = (g < 1024);
        int gg  = g & 1023;
        int row = gg >> 3;             // 0..127
        int gran = gg & 7;             // 16B granule within 128B row
        const __nv_bfloat16* src = (isA
            ? A + (size_t)(row0 + row)*DD
            : B + (size_t)(col0 + row)*DD) + kk + gran*8;
        uint32_t dst = stage_base + (isA ? 0u : 16384u)
                     + (uint32_t)row*128u + (uint32_t)((gran ^ (row & 7)) << 4);
        cp_async16(dst, src);
    }
}

__global__ void __launch_bounds__(256, 2)
lmhead_k(const __nv_bfloat16* __restrict__ Ah,
         const __nv_bfloat16* __restrict__ Al,
         const __nv_bfloat16* __restrict__ Bh,
         const __nv_bfloat16* __restrict__ Bl,
         const float* __restrict__ bias,
         float* __restrict__ C)
{
    extern __shared__ char smem[];
    const uint32_t sb = smem_u32(smem);
    const int tid  = threadIdx.x;
    const int wid  = tid >> 5;
    const int lane = tid & 31;
    const int row0 = blockIdx.x * 128;
    const int col0 = blockIdx.y * 128;

    const int warp_m = wid & 1;      // 2(m) x 4(n) warps; warp tile 64x32
    const int warp_n = wid >> 1;

    float acc[4][4][4];
    #pragma unroll
    for (int i = 0; i < 4; i++)
        #pragma unroll
        for (int j = 0; j < 4; j++)
            #pragma unroll
            for (int q = 0; q < 4; q++) acc[i][j][q] = 0.f;

    // chunk -> (A source, B source, k offset)
    #define SEG_A(c) ((c) < 16 ? Ah : Al)
    #define SEG_B(c) (((c) >= 8 && (c) < 16) ? Bl : Bh)
    #define SEG_K(c) (((c) & 7) * 64)

    load_stage_lm(SEG_A(0), SEG_B(0), row0, col0, SEG_K(0), sb,                 tid); CP_COMMIT();
    load_stage_lm(SEG_A(1), SEG_B(1), row0, col0, SEG_K(1), sb + L_STAGE_BYTES, tid); CP_COMMIT();

    const int a_row  = warp_m*64 + (lane & 15);
    const int a_gsel = lane >> 4;
    const int b_row  = warp_n*32 + ((lane >> 4) << 3) + (lane & 7);
    const int b_gsel = (lane >> 3) & 1;

    for (int c = 0; c < NCH_LM; c++) {
        cp_wait<L_STAGES-2>();
        __syncthreads();

        if (c + 2 < NCH_LM) {
            int nc = c + 2;
            load_stage_lm(SEG_A(nc), SEG_B(nc), row0, col0, SEG_K(nc),
                          sb + (nc%L_STAGES)*L_STAGE_BYTES, tid);
        }
        CP_COMMIT();

        const uint32_t sA = sb + (c%L_STAGES)*L_STAGE_BYTES;
        const uint32_t sB = sA + 16384u;

        #pragma unroll
        for (int s = 0; s < 4; s++) {   // four k16 steps per 64-chunk
            uint32_t a[4][4];
            #pragma unroll
            for (int mi = 0; mi < 4; mi++) {
                int r = a_row + mi*16;
                int g = 2*s + a_gsel;
                uint32_t addr = sA + (uint32_t)r*128u + (uint32_t)((g ^ (r & 7)) << 4);
                ldmatrix_x4(a[mi][0], a[mi][1], a[mi][2], a[mi][3], addr);
            }
            uint32_t b[4][2];
            #pragma unroll
            for (int ng = 0; ng < 2; ng++) {
                int r = b_row + ng*16;
                int g = 2*s + b_gsel;
                uint32_t addr = sB + (uint32_t)r*128u + (uint32_t)((g ^ (r & 7)) << 4);
                uint32_t r0, r1, r2, r3;
                ldmatrix_x4(r0, r1, r2, r3, addr);
                b[ng*2+0][0] = r0; b[ng*2+0][1] = r1;
                b[ng*2+1][0] = r2; b[ng*2+1][1] = r3;
            }
            #pragma unroll
            for (int mi = 0; mi < 4; mi++)
                #pragma unroll
                for (int nj = 0; nj < 4; nj++)
                    mma_bf16(acc[mi][nj], a[mi][0], a[mi][1], a[mi][2], a[mi][3],
                             b[nj][0], b[nj][1]);
        }
    }

    const int trow = lane >> 2;
    const int tcol = (lane & 3) * 2;
    #pragma unroll
    for (int mi = 0; mi < 4; mi++) {
        const int mbase = row0 + warp_m*64 + mi*16 + trow;
        #pragma unroll
        for (int nj = 0; nj < 4; nj++) {
            const int col = col0 + warp_n*32 + nj*8 + tcol;
            const float b0 = __ldg(bias + col);
            const float b1 = __ldg(bias + col + 1);
            *(float2*)(C + (size_t)mbase*VV + col) =
                make_float2(acc[mi][nj][0] + b0, acc[mi][nj][1] + b1);
            *(float2*)(C + (size_t)(mbase+8)*VV + col) =
                make_float2(acc[mi][nj][2] + b0, acc[mi][nj][3] + b1);
        }
    }
}

// ---------------------------------------------------------------------------
// Host side
// ---------------------------------------------------------------------------
static void run_gat_layer(const float* xin, const float* a,
                          const float* ow, const float* ob, float* xout,
                          float* wx, float* ssrc, float* sdst, float* agg,
                          __nv_bfloat16* Ap, __nv_bfloat16* Wp,
                          bool wp_ready, const float* Wl)
{
    dim3 gg(NN/128, DD/128);
    if (!wp_ready) conv_B_k<<<(DD*(DD/4))/256, 256>>>(Wl, Wp);
    conv_A_k<<<(NN*(DD/4))/256, 256>>>(xin, Ap);
    gat_mma_k<0><<<gg, 256, G_SMEM>>>(Ap, Wp, nullptr, wx);
    scores_k<<<(NN*HH*32)/256, 256>>>(wx, a, ssrc, sdst);
    attn_k<<<NN, 128>>>(wx, ssrc, sdst, agg);
    conv_A_k<<<(NN*(DD/4))/256, 256>>>(agg, Ap);
    conv_B_k<<<(DD*(DD/4))/256, 256>>>(ow, Wp);
    gat_mma_k<1><<<gg, 256, G_SMEM>>>(Ap, Wp, ob, xout);
}

extern "C" void kernel_launch(void* const* d_in, const int* in_sizes, int n_in,
                              void* d_out, int out_size)
{
    const int*   ids = (const int*)  d_in[0];
    const float* emb = (const float*)d_in[1];
    const float* W1  = (const float*)d_in[2];
    const float* a1  = (const float*)d_in[3];
    const float* o1w = (const float*)d_in[4];
    const float* o1b = (const float*)d_in[5];
    const float* W2  = (const float*)d_in[6];
    const float* a2  = (const float*)d_in[7];
    const float* o2w = (const float*)d_in[8];
    const float* o2b = (const float*)d_in[9];
    const float* lmw = (const float*)d_in[10];
    const float* lmb = (const float*)d_in[11];
    float* out = (float*)d_out;

    float *px, *px2, *pwx, *pagg, *pssrc, *psdst;
    __nv_bfloat16 *pAp, *pWp, *pAh, *pAl, *pBh, *pBl;
    cudaGetSymbolAddress((void**)&px,    g_x);
    cudaGetSymbolAddress((void**)&px2,   g_x2);
    cudaGetSymbolAddress((void**)&pwx,   g_wx);
    cudaGetSymbolAddress((void**)&pagg,  g_agg);
    cudaGetSymbolAddress((void**)&pssrc, g_ssrc);
    cudaGetSymbolAddress((void**)&psdst, g_sdst);
    cudaGetSymbolAddress((void**)&pAp,   g_Ap);
    cudaGetSymbolAddress((void**)&pWp,   g_Wp);
    cudaGetSymbolAddress((void**)&pAh,   g_Ah);
    cudaGetSymbolAddress((void**)&pAl,   g_Al);
    cudaGetSymbolAddress((void**)&pBh,   g_Bh);
    cudaGetSymbolAddress((void**)&pBl,   g_Bl);

    static bool attr_set = false;
    if (!attr_set) {
        cudaFuncSetAttribute(lmhead_k,     cudaFuncAttributeMaxDynamicSharedMemorySize, L_SMEM);
        cudaFuncSetAttribute(gat_mma_k<0>, cudaFuncAttributeMaxDynamicSharedMemorySize, G_SMEM);
        cudaFuncSetAttribute(gat_mma_k<1>, cudaFuncAttributeMaxDynamicSharedMemorySize, G_SMEM);
        attr_set = true;
    }

    // Launch 1: LM-head weight split (hi/lo)
    conv_hl_k<<<(VV*(DD/4))/256, 256>>>(lmw, pBh, pBl);
    // Launch 2: embedding gather
    gather_k<<<(NN*DD/4)/256, 256>>>(ids, emb, px);
    // Launch 3: GAT layer-1 weight split (hoisted so probe is launch #4)
    conv_B_k<<<(DD*(DD/4))/256, 256>>>(W1, pWp);
    // Launch 4: lmhead PROBE (small grid; rows overwritten by final lmhead —
    // ncu captures launch #4, giving the lmhead profile each round).
    {
        dim3 gp(1, VV/128);
        lmhead_k<<<gp, 256, L_SMEM>>>(pAh, pAl, pBh, pBl, lmb, out);
    }

    run_gat_layer(px,  a1, o1w, o1b, px2, pwx, pssrc, psdst, pagg, pAp, pWp, true,  W1);
    run_gat_layer(px2, a2, o2w, o2b, px,  pwx, pssrc, psdst, pagg, pAp, pWp, false, W2);

    // LM-head activation split
    conv_hl_k<<<(NN*(DD/4))/256, 256>>>(px, pAh, pAl);

    // LM head: grid.x = M blocks (fast-varying -> B-tile L2 reuse)
    dim3 g(NN/128, VV/128);
    lmhead_k<<<g, 256, L_SMEM>>>(pAh, pAl, pBh, pBl, lmb, out);
}

// round 7
// speedup vs baseline: 1.0373x; 1.0373x over previous
#include <cuda_runtime.h>
#include <cuda_bf16.h>
#include <math.h>
#include <stdint.h>

// Problem constants (fixed by the reference)
#define BB 2
#define SS 2048
#define DD 512
#define VV 32000
#define HH 4
#define DH 128
#define WW 3
#define NN (BB*SS)   // 4096
#define KP 1536      // GAT split-bf16 K' = 3*512
#define NCH_GAT 24   // KP / 64
#define NCH_LM  8    // 512 / 64 (fused 3-product loop)

// Scratch (device globals; no allocation allowed)
__device__ float g_x   [NN*DD];
__device__ float g_x2  [NN*DD];
__device__ float g_wx  [NN*DD];
__device__ float g_agg [NN*DD];
__device__ float g_ssrc[NN*HH];
__device__ float g_sdst[NN*HH];
__device__ __nv_bfloat16 g_Ap[(size_t)NN*KP];   // GAT A split [Ah|Ah|Al]
__device__ __nv_bfloat16 g_Wp[(size_t)DD*KP];   // GAT W split [Bh|Bl|Bh]
__device__ __nv_bfloat16 g_Ah[(size_t)NN*DD];   // LM head A hi
__device__ __nv_bfloat16 g_Al[(size_t)NN*DD];   // LM head A lo
__device__ __nv_bfloat16 g_Bh[(size_t)VV*DD];   // LM head B hi
__device__ __nv_bfloat16 g_Bl[(size_t)VV*DD];   // LM head B lo

// ---------------------------------------------------------------------------
// PTX helpers (sm_80-era: cp.async, ldmatrix, mma.sync — valid at compute_103.
// tcgen05 is NOT available at the harness's virtual PTX target.)
// ---------------------------------------------------------------------------
__device__ __forceinline__ uint32_t smem_u32(const void* p) {
    uint32_t a;
    asm("{ .reg .u64 t; cvta.to.shared.u64 t, %1; cvt.u32.u64 %0, t; }"
        : "=r"(a) : "l"(p));
    return a;
}
__device__ __forceinline__ void cp_async16(uint32_t dst, const void* src) {
    asm volatile("cp.async.cg.shared.global [%0], [%1], 16;\n" :: "r"(dst), "l"(src));
}
#define CP_COMMIT() asm volatile("cp.async.commit_group;\n" ::: "memory")
template<int Nw> __device__ __forceinline__ void cp_wait() {
    asm volatile("cp.async.wait_group %0;\n" :: "n"(Nw) : "memory");
}
__device__ __forceinline__ void ldmatrix_x4(uint32_t& r0, uint32_t& r1,
                                            uint32_t& r2, uint32_t& r3, uint32_t addr) {
    asm volatile("ldmatrix.sync.aligned.m8n8.x4.shared.b16 {%0,%1,%2,%3}, [%4];\n"
                 : "=r"(r0), "=r"(r1), "=r"(r2), "=r"(r3) : "r"(addr));
}
__device__ __forceinline__ void mma_bf16(float* c,
                                         uint32_t a0, uint32_t a1, uint32_t a2, uint32_t a3,
                                         uint32_t b0, uint32_t b1) {
    asm volatile(
        "mma.sync.aligned.m16n8k16.row.col.f32.bf16.bf16.f32 "
        "{%0,%1,%2,%3}, {%4,%5,%6,%7}, {%8,%9}, {%0,%1,%2,%3};\n"
        : "+f"(c[0]), "+f"(c[1]), "+f"(c[2]), "+f"(c[3])
        : "r"(a0), "r"(a1), "r"(a2), "r"(a3), "r"(b0), "r"(b1));
}

// ---------------------------------------------------------------------------
// Embedding gather
// ---------------------------------------------------------------------------
__global__ void gather_k(const int* __restrict__ ids,
                         const float* __restrict__ emb,
                         float* __restrict__ x)
{
    int idx = blockIdx.x * blockDim.x + threadIdx.x;
    int n  = idx / (DD/4);
    int d4 = idx % (DD/4);
    const float4* srcp = (const float4*)(emb + (size_t)ids[n]*DD) + d4;
    float4* dstp = (float4*)(x + (size_t)n*DD) + d4;
    *dstp = *srcp;
}

// ---------------------------------------------------------------------------
// GAT conversions: fp32 -> K-concatenated bf16 splits
// ---------------------------------------------------------------------------
__global__ void conv_A_k(const float* __restrict__ src, __nv_bfloat16* __restrict__ dst)
{
    size_t i = (size_t)blockIdx.x * blockDim.x + threadIdx.x;
    size_t r = i / (DD/4);
    int c = (int)(i % (DD/4)) * 4;
    float4 v = *(const float4*)(src + r*DD + c);
    float f[4] = {v.x, v.y, v.z, v.w};
    __nv_bfloat16* base = dst + r*KP + c;
    #pragma unroll
    for (int j = 0; j < 4; j++) {
        __nv_bfloat16 h = __float2bfloat16(f[j]);
        __nv_bfloat16 l = __float2bfloat16(f[j] - __bfloat162float(h));
        base[j]        = h;
        base[512 + j]  = h;
        base[1024 + j] = l;
    }
}
__global__ void conv_B_k(const float* __restrict__ src, __nv_bfloat16* __restrict__ dst)
{
    size_t i = (size_t)blockIdx.x * blockDim.x + threadIdx.x;
    size_t r = i / (DD/4);
    int c = (int)(i % (DD/4)) * 4;
    float4 v = *(const float4*)(src + r*DD + c);
    float f[4] = {v.x, v.y, v.z, v.w};
    __nv_bfloat16* base = dst + r*KP + c;
    #pragma unroll
    for (int j = 0; j < 4; j++) {
        __nv_bfloat16 h = __float2bfloat16(f[j]);
        __nv_bfloat16 l = __float2bfloat16(f[j] - __bfloat162float(h));
        base[j]        = h;
        base[512 + j]  = l;
        base[1024 + j] = h;
    }
}

// ---------------------------------------------------------------------------
// LM-head conversions: fp32 -> (hi, lo) bf16 pair arrays
// ---------------------------------------------------------------------------
__global__ void conv_hl_k(const float* __restrict__ src,
                          __nv_bfloat16* __restrict__ dh, __nv_bfloat16* __restrict__ dl)
{
    size_t i = (size_t)blockIdx.x * blockDim.x + threadIdx.x;
    size_t r = i / (DD/4);
    int c = (int)(i % (DD/4)) * 4;
    float4 v = *(const float4*)(src + r*DD + c);
    float f[4] = {v.x, v.y, v.z, v.w};
    #pragma unroll
    for (int j = 0; j < 4; j++) {
        __nv_bfloat16 h = __float2bfloat16(f[j]);
        __nv_bfloat16 l = __float2bfloat16(f[j] - __bfloat162float(h));
        dh[r*DD + c + j] = h;
        dl[r*DD + c + j] = l;
    }
}

// ---------------------------------------------------------------------------
// Per-node attention scores
// ---------------------------------------------------------------------------
__global__ void scores_k(const float* __restrict__ wx,
                         const float* __restrict__ a,
                         float* __restrict__ ssrc,
                         float* __restrict__ sdst)
{
    int w    = (blockIdx.x * blockDim.x + threadIdx.x) >> 5;
    int lane = threadIdx.x & 31;
    if (w >= NN*HH) return;
    int n = w / HH, h = w % HH;
    const float* row = wx + (size_t)n*DD + h*DH;
    const float* au  = a + (size_t)h*2*DH;
    const float* av  = au + DH;

    int d = lane * 4;
    float4 x = *(const float4*)(row + d);
    float4 u = *(const float4*)(au  + d);
    float4 v = *(const float4*)(av  + d);
    float s1 = x.x*u.x + x.y*u.y + x.z*u.z + x.w*u.w;
    float s2 = x.x*v.x + x.y*v.y + x.z*v.z + x.w*v.w;
    #pragma unroll
    for (int o = 16; o; o >>= 1) {
        s1 += __shfl_xor_sync(0xffffffffu, s1, o);
        s2 += __shfl_xor_sync(0xffffffffu, s2, o);
    }
    if (lane == 0) { ssrc[w] = s1; sdst[w] = s2; }
}

// ---------------------------------------------------------------------------
// Windowed GAT aggregation
// ---------------------------------------------------------------------------
__global__ void attn_k(const float* __restrict__ wx,
                       const float* __restrict__ ssrc,
                       const float* __restrict__ sdst,
                       float* __restrict__ agg)
{
    int n    = blockIdx.x;
    int h    = threadIdx.x >> 5;
    int lane = threadIdx.x & 31;
    int i    = n % SS;

    float sd = sdst[(size_t)n*HH + h];

    float e[2*WW];
    int   jn[2*WW];
    int cnt = 0;
    #pragma unroll
    for (int off = -WW; off <= WW; off++) {
        if (off == 0) continue;
        int ji = i + off;
        if (ji < 0 || ji >= SS) continue;
        int j = n + off;
        float v = ssrc[(size_t)j*HH + h] + sd;
        v = v >= 0.f ? v : 0.2f * v;
        e[cnt] = v; jn[cnt] = j; cnt++;
    }
    float m = -1e30f;
    for (int c = 0; c < cnt; c++) m = fmaxf(m, e[c]);
    float den = 0.f;
    for (int c = 0; c < cnt; c++) { e[c] = expf(e[c] - m); den += e[c]; }
    float inv = 1.f / (den + 1e-16f);

    int d = lane * 4;
    float4 accv = make_float4(0.f, 0.f, 0.f, 0.f);
    for (int c = 0; c < cnt; c++) {
        const float4 xv = *(const float4*)(wx + (size_t)jn[c]*DD + h*DH + d);
        float al = e[c] * inv;
        accv.x = fmaf(al, xv.x, accv.x);
        accv.y = fmaf(al, xv.y, accv.y);
        accv.z = fmaf(al, xv.z, accv.z);
        accv.w = fmaf(al, xv.w, accv.w);
    }
    *(float4*)(agg + (size_t)n*DD + h*DH + d) = accv;
}

// ---------------------------------------------------------------------------
// GAT mma GEMM (split-bf16 K'=1536): unchanged (passing, small share of time)
// ---------------------------------------------------------------------------
#define G_STAGES 3
#define G_STAGE_BYTES 32768
#define G_SMEM (G_STAGES*G_STAGE_BYTES)

__device__ __forceinline__ void load_stage_gat(
    const __nv_bfloat16* __restrict__ Ap, const __nv_bfloat16* __restrict__ Bp,
    int row0, int col0, int k0, uint32_t stage_base, int tid)
{
    #pragma unroll
    for (int it = 0; it < 8; it++) {
        int g = tid + it*256;
        bool isA = (g < 1024);
        int gg  = isA ? g : (g - 1024);
        int row = gg >> 3;
        int gran = gg & 7;
        const __nv_bfloat16* src = isA
            ? (Ap + (size_t)(row0 + row)*KP + k0 + gran*8)
            : (Bp + (size_t)(col0 + row)*KP + k0 + gran*8);
        uint32_t dst = stage_base + (isA ? 0u : 16384u)
                     + (uint32_t)row*128u + (uint32_t)((gran ^ (row & 7)) << 4);
        cp_async16(dst, src);
    }
}

template<int EPI>
__global__ void __launch_bounds__(256, 2)
gat_mma_k(const __nv_bfloat16* __restrict__ Ap,
          const __nv_bfloat16* __restrict__ Bp,
          const float* __restrict__ bias,
          float* __restrict__ C)
{
    extern __shared__ char smem[];
    const uint32_t sb = smem_u32(smem);
    const int tid  = threadIdx.x;
    const int wid  = tid >> 5;
    const int lane = tid & 31;
    const int row0 = blockIdx.x * 128;
    const int col0 = blockIdx.y * 128;

    const int warp_m = wid & 3;
    const int warp_n = wid >> 2;

    float acc[2][8][4];
    #pragma unroll
    for (int i = 0; i < 2; i++)
        #pragma unroll
        for (int j = 0; j < 8; j++)
            #pragma unroll
            for (int q = 0; q < 4; q++) acc[i][j][q] = 0.f;

    load_stage_gat(Ap, Bp, row0, col0, 0,  sb,                 tid); CP_COMMIT();
    load_stage_gat(Ap, Bp, row0, col0, 64, sb + G_STAGE_BYTES, tid); CP_COMMIT();

    const int a_row  = warp_m*32 + (lane & 15);
    const int a_gsel = lane >> 4;
    const int b_row  = warp_n*64 + ((lane >> 4) << 3) + (lane & 7);
    const int b_gsel = (lane >> 3) & 1;

    for (int c = 0; c < NCH_GAT; c++) {
        cp_wait<G_STAGES-2>();
        __syncthreads();

        if (c + 2 < NCH_GAT)
            load_stage_gat(Ap, Bp, row0, col0, (c+2)*64,
                           sb + ((c+2)%G_STAGES)*G_STAGE_BYTES, tid);
        CP_COMMIT();

        const uint32_t sA = sb + (c%G_STAGES)*G_STAGE_BYTES;
        const uint32_t sB = sA + 16384u;

        #pragma unroll
        for (int s = 0; s < 4; s++) {
            uint32_t a[2][4];
            #pragma unroll
            for (int mi = 0; mi < 2; mi++) {
                int r = a_row + mi*16;
                int gran = 2*s + a_gsel;
                uint32_t addr = sA + (uint32_t)r*128u + (uint32_t)((gran ^ (r & 7)) << 4);
                ldmatrix_x4(a[mi][0], a[mi][1], a[mi][2], a[mi][3], addr);
            }
            uint32_t b[8][2];
            #pragma unroll
            for (int ng = 0; ng < 4; ng++) {
                int r = b_row + ng*16;
                int gran = 2*s + b_gsel;
                uint32_t addr = sB + (uint32_t)r*128u + (uint32_t)((gran ^ (r & 7)) << 4);
                uint32_t r0, r1, r2, r3;
                ldmatrix_x4(r0, r1, r2, r3, addr);
                b[ng*2+0][0] = r0; b[ng*2+0][1] = r1;
                b[ng*2+1][0] = r2; b[ng*2+1][1] = r3;
            }
            #pragma unroll
            for (int mi = 0; mi < 2; mi++)
                #pragma unroll
                for (int nj = 0; nj < 8; nj++)
                    mma_bf16(acc[mi][nj], a[mi][0], a[mi][1], a[mi][2], a[mi][3],
                             b[nj][0], b[nj][1]);
        }
    }

    const int trow = lane >> 2;
    const int tcol = (lane & 3) * 2;
    #pragma unroll
    for (int mi = 0; mi < 2; mi++) {
        const int mbase = row0 + warp_m*32 + mi*16 + trow;
        #pragma unroll
        for (int nj = 0; nj < 8; nj++) {
            const int col = col0 + warp_n*64 + nj*8 + tcol;
            float vv[4] = {acc[mi][nj][0], acc[mi][nj][1], acc[mi][nj][2], acc[mi][nj][3]};
            if (EPI == 1) {
                const float b0 = __ldg(bias + col);
                const float b1 = __ldg(bias + col + 1);
                vv[0] += b0; vv[1] += b1; vv[2] += b0; vv[3] += b1;
                #pragma unroll
                for (int q = 0; q < 4; q++)
                    vv[q] = vv[q] > 0.f ? vv[q] : (expf(vv[q]) - 1.f);
            }
            *(float2*)(C + (size_t)mbase*DD + col)     = make_float2(vv[0], vv[1]);
            *(float2*)(C + (size_t)(mbase+8)*DD + col) = make_float2(vv[2], vv[3]);
        }
    }
}

// ---------------------------------------------------------------------------
// LM head v5: fused 3-product split-bf16 with SHARED FRAGMENTS.
// C = Ah@Bh^T + Ah@Bl^T + Al@Bh^T + bias, ONE K loop (8 chunks of 64):
// per chunk load Ah/Al/Bh/Bl tiles, Ah frags reused for Bh & Bl, Bh frags for
// Ah & Al -> smem bytes/MAC drops 33%. CTA 128x256, 8 warps of 64x64, 2-stage.
// ---------------------------------------------------------------------------
#define L_STAGES 2
#define L_STAGE_BYTES 98304   // Ah 16K + Al 16K + Bh 32K + Bl 32K
#define L_SMEM (L_STAGES*L_STAGE_BYTES)
#define L_OFF_AL 16384u
#define L_OFF_BH 32768u
#define L_OFF_BL 65536u

__device__ __forceinline__ void load_stage_lm(
    const __nv_bfloat16* __restrict__ Ah, const __nv_bfloat16* __restrict__ Al,
    const __nv_bfloat16* __restrict__ Bh, const __nv_bfloat16* __restrict__ Bl,
    int row0, int col0, int kk, uint32_t stage_base, int tid)
{
    #pragma unroll
    for (int it = 0; it < 24; it++) {
        int g = tid + it*256;              // 0..6143 granules of 16B
        const __nv_bfloat16* basep;
        uint32_t soff;
        int gg;
        if (g < 2048) {                    // A: 2 x 1024 granules
            gg = g & 1023;
            basep = (g < 1024 ? Ah : Al) + (size_t)(row0 + (gg >> 3))*DD;
            soff  = (g < 1024 ? 0u : L_OFF_AL);
        } else {                           // B: 2 x 2048 granules
            int h = g - 2048;
            gg = h & 2047;
            basep = (h < 2048 ? Bh : Bl) + (size_t)(col0 + (gg >> 3))*DD;
            soff  = (h < 2048 ? L_OFF_BH : L_OFF_BL);
        }
        int row  = gg >> 3;
        int gran = gg & 7;
        uint32_t dst = stage_base + soff
                     + (uint32_t)row*128u + (uint32_t)((gran ^ (row & 7)) << 4);
        cp_async16(dst, basep + kk + gran*8);
    }
}

__global__ void __launch_bounds__(256, 1)
lmhead_k(const __nv_bfloat16* __restrict__ Ah,
         const __nv_bfloat16* __restrict__ Al,
         const __nv_bfloat16* __restrict__ Bh,
         const __nv_bfloat16* __restrict__ Bl,
         const float* __restrict__ bias,
         float* __restrict__ C)
{
    extern __shared__ char smem[];
    const uint32_t sb = smem_u32(smem);
    const int tid  = threadIdx.x;
    const int wid  = tid >> 5;
    const int lane = tid & 31;
    const int row0 = blockIdx.x * 128;
    const int col0 = blockIdx.y * 256;

    const int warp_m = wid & 1;      // 2(m) x 4(n) warps; warp tile 64x64
    const int warp_n = wid >> 1;

    float acc[4][8][4];
    #pragma unroll
    for (int i = 0; i < 4; i++)
        #pragma unroll
        for (int j = 0; j < 8; j++)
            #pragma unroll
            for (int q = 0; q < 4; q++) acc[i][j][q] = 0.f;

    // prologue: chunk 0 -> stage 0
    load_stage_lm(Ah, Al, Bh, Bl, row0, col0, 0, sb, tid);
    CP_COMMIT();

    const int a_row  = warp_m*64 + (lane & 15);
    const int a_gsel = lane >> 4;
    const int b_row  = warp_n*64 + ((lane >> 4) << 3) + (lane & 7);
    const int b_gsel = (lane >> 3) & 1;

    for (int c = 0; c < NCH_LM; c++) {
        // prefetch next chunk into the other stage
        if (c + 1 < NCH_LM)
            load_stage_lm(Ah, Al, Bh, Bl, row0, col0, (c+1)*64,
                          sb + ((c+1)&1)*L_STAGE_BYTES, tid);
        CP_COMMIT();
        cp_wait<1>();      // chunk c landed (the c+1 group may be in flight)
        __syncthreads();

        const uint32_t st  = sb + (c&1)*L_STAGE_BYTES;
        const uint32_t sAh = st;
        const uint32_t sAl = st + L_OFF_AL;
        const uint32_t sBh = st + L_OFF_BH;
        const uint32_t sBl = st + L_OFF_BL;

        #pragma unroll
        for (int s = 0; s < 4; s++) {   // four k16 steps per 64-chunk
            uint32_t aH[4][4], aL[4][4];
            #pragma unroll
            for (int mi = 0; mi < 4; mi++) {
                int r = a_row + mi*16;
                int g = 2*s + a_gsel;
                uint32_t sw = (uint32_t)r*128u + (uint32_t)((g ^ (r & 7)) << 4);
                ldmatrix_x4(aH[mi][0], aH[mi][1], aH[mi][2], aH[mi][3], sAh + sw);
                ldmatrix_x4(aL[mi][0], aL[mi][1], aL[mi][2], aL[mi][3], sAl + sw);
            }
            uint32_t bH[8][2], bL[8][2];
            #pragma unroll
            for (int ng = 0; ng < 4; ng++) {
                int r = b_row + ng*16;
                int g = 2*s + b_gsel;
                uint32_t sw = (uint32_t)r*128u + (uint32_t)((g ^ (r & 7)) << 4);
                uint32_t r0, r1, r2, r3;
                ldmatrix_x4(r0, r1, r2, r3, sBh + sw);
                bH[ng*2+0][0] = r0; bH[ng*2+0][1] = r1;
                bH[ng*2+1][0] = r2; bH[ng*2+1][1] = r3;
                ldmatrix_x4(r0, r1, r2, r3, sBl + sw);
                bL[ng*2+0][0] = r0; bL[ng*2+0][1] = r1;
                bL[ng*2+1][0] = r2; bL[ng*2+1][1] = r3;
            }
            // three products, shared fragments
            #pragma unroll
            for (int mi = 0; mi < 4; mi++)
                #pragma unroll
                for (int nj = 0; nj < 8; nj++) {
                    mma_bf16(acc[mi][nj], aH[mi][0], aH[mi][1], aH[mi][2], aH[mi][3],
                             bH[nj][0], bH[nj][1]);
                    mma_bf16(acc[mi][nj], aH[mi][0], aH[mi][1], aH[mi][2], aH[mi][3],
                             bL[nj][0], bL[nj][1]);
                    mma_bf16(acc[mi][nj], aL[mi][0], aL[mi][1], aL[mi][2], aL[mi][3],
                             bH[nj][0], bH[nj][1]);
                }
        }
        __syncthreads();   // stage consumed before refill next iteration
    }

    const int trow = lane >> 2;
    const int tcol = (lane & 3) * 2;
    #pragma unroll
    for (int mi = 0; mi < 4; mi++) {
        const int mbase = row0 + warp_m*64 + mi*16 + trow;
        #pragma unroll
        for (int nj = 0; nj < 8; nj++) {
            const int col = col0 + warp_n*64 + nj*8 + tcol;
            const float b0 = __ldg(bias + col);
            const float b1 = __ldg(bias + col + 1);
            *(float2*)(C + (size_t)mbase*VV + col) =
                make_float2(acc[mi][nj][0] + b0, acc[mi][nj][1] + b1);
            *(float2*)(C + (size_t)(mbase+8)*VV + col) =
                make_float2(acc[mi][nj][2] + b0, acc[mi][nj][3] + b1);
        }
    }
}

// ---------------------------------------------------------------------------
// Host side
// ---------------------------------------------------------------------------
static void run_gat_layer(const float* xin, const float* a,
                          const float* ow, const float* ob, float* xout,
                          float* wx, float* ssrc, float* sdst, float* agg,
                          __nv_bfloat16* Ap, __nv_bfloat16* Wp,
                          bool wp_ready, const float* Wl)
{
    dim3 gg(NN/128, DD/128);
    if (!wp_ready) conv_B_k<<<(DD*(DD/4))/256, 256>>>(Wl, Wp);
    conv_A_k<<<(NN*(DD/4))/256, 256>>>(xin, Ap);
    gat_mma_k<0><<<gg, 256, G_SMEM>>>(Ap, Wp, nullptr, wx);
    scores_k<<<(NN*HH*32)/256, 256>>>(wx, a, ssrc, sdst);
    attn_k<<<NN, 128>>>(wx, ssrc, sdst, agg);
    conv_A_k<<<(NN*(DD/4))/256, 256>>>(agg, Ap);
    conv_B_k<<<(DD*(DD/4))/256, 256>>>(ow, Wp);
    gat_mma_k<1><<<gg, 256, G_SMEM>>>(Ap, Wp, ob, xout);
}

extern "C" void kernel_launch(void* const* d_in, const int* in_sizes, int n_in,
                              void* d_out, int out_size)
{
    const int*   ids = (const int*)  d_in[0];
    const float* emb = (const float*)d_in[1];
    const float* W1  = (const float*)d_in[2];
    const float* a1  = (const float*)d_in[3];
    const float* o1w = (const float*)d_in[4];
    const float* o1b = (const float*)d_in[5];
    const float* W2  = (const float*)d_in[6];
    const float* a2  = (const float*)d_in[7];
    const float* o2w = (const float*)d_in[8];
    const float* o2b = (const float*)d_in[9];
    const float* lmw = (const float*)d_in[10];
    const float* lmb = (const float*)d_in[11];
    float* out = (float*)d_out;

    float *px, *px2, *pwx, *pagg, *pssrc, *psdst;
    __nv_bfloat16 *pAp, *pWp, *pAh, *pAl, *pBh, *pBl;
    cudaGetSymbolAddress((void**)&px,    g_x);
    cudaGetSymbolAddress((void**)&px2,   g_x2);
    cudaGetSymbolAddress((void**)&pwx,   g_wx);
    cudaGetSymbolAddress((void**)&pagg,  g_agg);
    cudaGetSymbolAddress((void**)&pssrc, g_ssrc);
    cudaGetSymbolAddress((void**)&psdst, g_sdst);
    cudaGetSymbolAddress((void**)&pAp,   g_Ap);
    cudaGetSymbolAddress((void**)&pWp,   g_Wp);
    cudaGetSymbolAddress((void**)&pAh,   g_Ah);
    cudaGetSymbolAddress((void**)&pAl,   g_Al);
    cudaGetSymbolAddress((void**)&pBh,   g_Bh);
    cudaGetSymbolAddress((void**)&pBl,   g_Bl);

    static bool attr_set = false;
    if (!attr_set) {
        cudaFuncSetAttribute(lmhead_k,     cudaFuncAttributeMaxDynamicSharedMemorySize, L_SMEM);
        cudaFuncSetAttribute(gat_mma_k<0>, cudaFuncAttributeMaxDynamicSharedMemorySize, G_SMEM);
        cudaFuncSetAttribute(gat_mma_k<1>, cudaFuncAttributeMaxDynamicSharedMemorySize, G_SMEM);
        attr_set = true;
    }

    // Launch 1: LM-head weight split (hi/lo)
    conv_hl_k<<<(VV*(DD/4))/256, 256>>>(lmw, pBh, pBl);
    // Launch 2: embedding gather
    gather_k<<<(NN*DD/4)/256, 256>>>(ids, emb, px);
    // Launch 3: GAT layer-1 weight split (hoisted so probe is launch #4)
    conv_B_k<<<(DD*(DD/4))/256, 256>>>(W1, pWp);
    // Launch 4: lmhead PROBE (small grid; rows overwritten by final lmhead —
    // ncu captures launch #4, giving the lmhead profile each round).
    {
        dim3 gp(1, VV/256);
        lmhead_k<<<gp, 256, L_SMEM>>>(pAh, pAl, pBh, pBl, lmb, out);
    }

    run_gat_layer(px,  a1, o1w, o1b, px2, pwx, pssrc, psdst, pagg, pAp, pWp, true,  W1);
    run_gat_layer(px2, a2, o2w, o2b, px,  pwx, pssrc, psdst, pagg, pAp, pWp, false, W2);

    // LM-head activation split
    conv_hl_k<<<(NN*(DD/4))/256, 256>>>(px, pAh, pAl);

    // LM head: grid.x = M blocks (fast-varying -> B-tile L2 reuse)
    dim3 g(NN/128, VV/256);
    lmhead_k<<<g, 256, L_SMEM>>>(pAh, pAl, pBh, pBl, lmb, out);
}